// round 6
// baseline (speedup 1.0000x reference)
#include <cuda_runtime.h>
#include <cuda_fp16.h>
#include <cstdint>

// ---------------------------------------------------------------------------
// Problem constants
// ---------------------------------------------------------------------------
#define BATCH    8192
#define IN_SIZE  512
#define OUT_SIZE 512
#define KDIM     (IN_SIZE * 8)        // 4096

// GEMM tiling
#define BM       128
#define BN       128
#define BK       64                    // 64 fp16 = 128 B rows
#define STAGES   4
#define NTILES_N (OUT_SIZE / BN)       // 4
#define NTILES_M (BATCH / BM)          // 64
#define NKC      (KDIM / BK)           // 64
#define TOTAL_UNITS (NTILES_M * NTILES_N * NKC)   // 16384
#define A_BYTES  (BM * 128)
#define B_BYTES  (BN * 128)
#define STAGE_BYTES (A_BYTES + B_BYTES)
#define SMEM_TOTAL  (STAGES * STAGE_BYTES)   // 131072

// ---------------------------------------------------------------------------
// Scratch (device globals -- no cudaMalloc allowed)
// ---------------------------------------------------------------------------
__device__ __half g_B[(size_t)OUT_SIZE * KDIM];   // 4 MB: coeff*weight, fp16

__device__ __forceinline__ uint32_t smem_u32(const void* p) {
    uint32_t a;
    asm("{ .reg .u64 t; cvta.to.shared.u64 t, %1; cvt.u32.u64 %0, t; }"
        : "=r"(a) : "l"(p));
    return a;
}

// Closed-form uniform cubic B-spline: 8 basis values for one x, packed fp16.
__device__ __forceinline__ uint4 basis8(float xv) {
    xv = fminf(1.0f, fmaxf(-1.0f, xv));
    float u = (xv + 1.0f) * 3.5f;          // / h, h = 2/7
    int i = min(7, (int)u);
    float t = u - (float)i;
    const float k6 = 1.0f / 6.0f;
    float t2 = t * t, t3 = t2 * t, omt = 1.0f - t;
    float v0 = t3 * k6;                                  // d = 0  (j == i)
    float v1 = (1.0f + 3.0f * (t + t2 - t3)) * k6;       // d = 1
    float v2 = (4.0f - 6.0f * t2 + 3.0f * t3) * k6;      // d = 2
    float v3 = omt * omt * omt * k6;                     // d = 3  (j == i-3)
    float o[8];
#pragma unroll
    for (int j = 0; j < 8; j++) {
        int d = i - j;
        o[j] = (d == 0) ? v0 : (d == 1) ? v1 : (d == 2) ? v2
             : (d == 3) ? v3 : 0.0f;
    }
    union { uint4 uu; __half2 hh[4]; } v;
    v.hh[0] = __floats2half2_rn(o[0], o[1]);
    v.hh[1] = __floats2half2_rn(o[2], o[3]);
    v.hh[2] = __floats2half2_rn(o[4], o[5]);
    v.hh[3] = __floats2half2_rn(o[6], o[7]);
    return v.uu;
}

// ---------------------------------------------------------------------------
// Kernel 1: B matrix prep  g_B[o, i*8+g] = coeff[o,i,g] * w[o,i]  (fp16)
// ---------------------------------------------------------------------------
__global__ void prep_kernel(const float* __restrict__ w, const float* __restrict__ coef) {
    int idx = blockIdx.x * blockDim.x + threadIdx.x;   // (o, i)
    float wv = w[idx];
    const float4* c4 = reinterpret_cast<const float4*>(coef) + (size_t)idx * 2;
    float4 a = c4[0], b = c4[1];
    union { uint4 u; __half2 h[4]; } v;
    v.h[0] = __floats2half2_rn(a.x * wv, a.y * wv);
    v.h[1] = __floats2half2_rn(a.z * wv, a.w * wv);
    v.h[2] = __floats2half2_rn(b.x * wv, b.y * wv);
    v.h[3] = __floats2half2_rn(b.z * wv, b.w * wv);
    reinterpret_cast<uint4*>(g_B)[idx] = v.u;
}

// ---------------------------------------------------------------------------
// Kernel 2: fused stream-K persistent GEMM
//   out[8192,512] += S(x)[8192,4096] @ B[512,4096]^T   (out pre-zeroed)
// S is never materialized in gmem: each thread LDGs a float4 of x for chunk
// g+2 at loop top (latency hidden by the mma loop), computes 4 basis cells
// (1 cell = 8 fp16 = one swizzled 16B chunk) and STS's them into the stage-A
// region after the mma loop; the end-of-iteration wait+syncthreads publishes
// A(g+2) before its first reader (iteration g+1's kk3 fragment prefetch).
// B arrives via cp.async. Register-level fragment double buffering as before.
// ---------------------------------------------------------------------------
__global__ void __launch_bounds__(256, 1) bspline_gemm_kernel(
    const float* __restrict__ x, float* __restrict__ out, int ncta)
{
    extern __shared__ char smem[];
    const uint32_t sb = smem_u32(smem);
    const int tid  = threadIdx.x;
    const int lane = tid & 31;
    const int warp = tid >> 5;
    const int wm   = warp & 1;    // 0..1  (64 rows)
    const int wn   = warp >> 1;   // 0..3  (32 cols)

    const int c0 = (int)((long long)blockIdx.x       * TOTAL_UNITS / ncta);
    const int c1 = (int)((long long)(blockIdx.x + 1) * TOTAL_UNITS / ncta);

    // this thread's fixed (row, i0) within any A tile
    const int arow = tid >> 1;            // 0..127
    const int ai0  = (tid & 1) * 4;       // 0 or 4

    // ---- B loader: 16 KB per chunk, 4 x 16B per thread --------------------
    auto load_chunkB = [&](int g) {
        const int kc    = g & 63;
        const int ntile = (g >> 6) & 3;
        const __half* gB = g_B + (size_t)ntile * BN * KDIM + kc * BK;
        const uint32_t base = sb + (g & 3) * STAGE_BYTES + A_BYTES;
#pragma unroll
        for (int t4 = 0; t4 < 4; t4++) {
            int cid = tid + t4 * 256;                // 0..1023
            int row = cid >> 3;
            int cc  = cid & 7;
            uint32_t soff = row * 128 + ((cc ^ (row & 7)) << 4);
            const __half* gb = gB + (size_t)row * KDIM + cc * 8;
            asm volatile("cp.async.cg.shared.global [%0], [%1], 16;"
                         :: "r"(base + soff), "l"(gb));
        }
    };

    // ---- A producers: LDG x, then basis -> STS into stage-A ---------------
    auto ldg_x = [&](int g) -> float4 {
        const int mtile = (g >> 6) >> 2;
        const int kc    = g & 63;
        return *reinterpret_cast<const float4*>(
            x + (size_t)(mtile * BM + arow) * IN_SIZE + kc * 8 + ai0);
    };
    auto sts_A = [&](int g, float4 xr) {
        const uint32_t sA = sb + (g & 3) * STAGE_BYTES;
        uint32_t a0 = sA + arow * 128 + (((ai0 + 0) ^ (arow & 7)) << 4);
        uint32_t a1 = sA + arow * 128 + (((ai0 + 1) ^ (arow & 7)) << 4);
        uint32_t a2 = sA + arow * 128 + (((ai0 + 2) ^ (arow & 7)) << 4);
        uint32_t a3 = sA + arow * 128 + (((ai0 + 3) ^ (arow & 7)) << 4);
        uint4 v;
        v = basis8(xr.x);
        asm volatile("st.shared.v4.b32 [%0], {%1,%2,%3,%4};"
                     :: "r"(a0), "r"(v.x), "r"(v.y), "r"(v.z), "r"(v.w));
        v = basis8(xr.y);
        asm volatile("st.shared.v4.b32 [%0], {%1,%2,%3,%4};"
                     :: "r"(a1), "r"(v.x), "r"(v.y), "r"(v.z), "r"(v.w));
        v = basis8(xr.z);
        asm volatile("st.shared.v4.b32 [%0], {%1,%2,%3,%4};"
                     :: "r"(a2), "r"(v.x), "r"(v.y), "r"(v.z), "r"(v.w));
        v = basis8(xr.w);
        asm volatile("st.shared.v4.b32 [%0], {%1,%2,%3,%4};"
                     :: "r"(a3), "r"(v.x), "r"(v.y), "r"(v.z), "r"(v.w));
    };

    // ---- fragment loader: chunk g, k16-step kk ----------------------------
    auto load_frags = [&](int g, int kk, uint32_t (*ar)[4], uint32_t (*br)[2]) {
        const uint32_t sA = sb + (g & 3) * STAGE_BYTES;
        const uint32_t sB = sA + A_BYTES;
#pragma unroll
        for (int mt = 0; mt < 4; mt++) {
            int row = wm * 64 + mt * 16 + (lane & 15);
            int kch = kk * 2 + (lane >> 4);
            uint32_t addr = sA + row * 128 + ((kch ^ (row & 7)) << 4);
            asm volatile("ldmatrix.sync.aligned.m8n8.x4.shared.b16 "
                         "{%0,%1,%2,%3}, [%4];"
                         : "=r"(ar[mt][0]), "=r"(ar[mt][1]),
                           "=r"(ar[mt][2]), "=r"(ar[mt][3])
                         : "r"(addr));
        }
#pragma unroll
        for (int nt2 = 0; nt2 < 2; nt2++) {
            int row = wn * 32 + nt2 * 16 + (lane & 7) + ((lane >> 4) << 3);
            int kch = kk * 2 + ((lane >> 3) & 1);
            uint32_t addr = sB + row * 128 + ((kch ^ (row & 7)) << 4);
            asm volatile("ldmatrix.sync.aligned.m8n8.x4.shared.b16 "
                         "{%0,%1,%2,%3}, [%4];"
                         : "=r"(br[nt2 * 2][0]),     "=r"(br[nt2 * 2][1]),
                           "=r"(br[nt2 * 2 + 1][0]), "=r"(br[nt2 * 2 + 1][1])
                         : "r"(addr));
        }
    };

    // ---- prologue ---------------------------------------------------------
#pragma unroll
    for (int p = 0; p < STAGES - 1; p++) {
        if (c0 + p < c1) load_chunkB(c0 + p);
        asm volatile("cp.async.commit_group;" ::: "memory");
    }
    if (c0 < c1)     sts_A(c0,     ldg_x(c0));
    if (c0 + 1 < c1) sts_A(c0 + 1, ldg_x(c0 + 1));
    asm volatile("cp.async.wait_group 1;" ::: "memory");
    __syncthreads();

    uint32_t ar[2][4][4], br[2][4][2];
    float acc[4][4][4] = {};

    load_frags(c0, 0, ar[0], br[0]);

    for (int g = c0; g < c1; g++) {
        // LDG x for chunk g+2 now; its STS happens after the mma loop.
        const bool haveA = (g + 2 < c1);
        float4 xr;
        if (haveA) xr = ldg_x(g + 2);

        if (g + STAGES - 1 < c1) load_chunkB(g + STAGES - 1);
        asm volatile("cp.async.commit_group;" ::: "memory");

#pragma unroll
        for (int kk = 0; kk < 4; kk++) {
            if (kk < 3)          load_frags(g,     kk + 1, ar[(kk + 1) & 1], br[(kk + 1) & 1]);
            else if (g + 1 < c1) load_frags(g + 1, 0,      ar[0],            br[0]);
            const int b = kk & 1;
#pragma unroll
            for (int mt = 0; mt < 4; mt++)
#pragma unroll
                for (int nt = 0; nt < 4; nt++)
                    asm volatile(
                        "mma.sync.aligned.m16n8k16.row.col.f32.f16.f16.f32 "
                        "{%0,%1,%2,%3}, {%4,%5,%6,%7}, {%8,%9}, {%0,%1,%2,%3};"
                        : "+f"(acc[mt][nt][0]), "+f"(acc[mt][nt][1]),
                          "+f"(acc[mt][nt][2]), "+f"(acc[mt][nt][3])
                        : "r"(ar[b][mt][0]), "r"(ar[b][mt][1]),
                          "r"(ar[b][mt][2]), "r"(ar[b][mt][3]),
                          "r"(br[b][nt][0]), "r"(br[b][nt][1]));
        }

        // build A for chunk g+2 (published by the sync below; first read at
        // iteration g+1's kk3 prefetch)
        if (haveA) sts_A(g + 2, xr);

        // ---- segment flush: tile finished, or end of this CTA's range -----
        if (((g & 63) == 63) || (g == c1 - 1)) {
            const int t     = g >> 6;
            const int mtile = t >> 2;
            const int ntile = t & 3;
#pragma unroll
            for (int mt = 0; mt < 4; mt++) {
                int r0 = mtile * BM + wm * 64 + mt * 16 + (lane >> 2);
#pragma unroll
                for (int nt = 0; nt < 4; nt++) {
                    int cc = ntile * BN + wn * 32 + nt * 8 + (lane & 3) * 2;
                    float* p0 = out + (size_t)r0 * OUT_SIZE + cc;
                    float* p1 = out + (size_t)(r0 + 8) * OUT_SIZE + cc;
                    atomicAdd(p0,     acc[mt][nt][0]);
                    atomicAdd(p0 + 1, acc[mt][nt][1]);
                    atomicAdd(p1,     acc[mt][nt][2]);
                    atomicAdd(p1 + 1, acc[mt][nt][3]);
                    acc[mt][nt][0] = 0.f; acc[mt][nt][1] = 0.f;
                    acc[mt][nt][2] = 0.f; acc[mt][nt][3] = 0.f;
                }
            }
        }

        // B stages <= g+2 complete; publishes sts_A(g+2) and guards stage reuse.
        asm volatile("cp.async.wait_group 1;" ::: "memory");
        __syncthreads();
    }
}

// ---------------------------------------------------------------------------
// Host: kernel_launch (graph-capturable, allocation-free)
// ---------------------------------------------------------------------------
extern "C" void kernel_launch(void* const* d_in, const int* in_sizes, int n_in,
                              void* d_out, int out_size) {
    const float* x    = (const float*)d_in[0];
    const float* w    = (const float*)d_in[1];
    const float* coef = (const float*)d_in[2];
    float*       out  = (float*)d_out;

    int nsm = 148;
    cudaDeviceGetAttribute(&nsm, cudaDevAttrMultiProcessorCount, 0);

    cudaMemsetAsync(out, 0, (size_t)BATCH * OUT_SIZE * sizeof(float));

    prep_kernel<<<(OUT_SIZE * IN_SIZE) / 256, 256>>>(w, coef);

    cudaFuncSetAttribute(bspline_gemm_kernel,
                         cudaFuncAttributeMaxDynamicSharedMemorySize, SMEM_TOTAL);
    bspline_gemm_kernel<<<nsm, 256, SMEM_TOTAL>>>(x, out, nsm);
}